// round 10
// baseline (speedup 1.0000x reference)
#include <cuda_runtime.h>
#include <cuda_fp16.h>
#include <stdint.h>

#define NF 128
#define NMAX 10000
#define THREADS 256
#define TE 128

// ===================== scratch =====================
__device__ float g_P[NMAX * NF];
__device__ float g_Q[NMAX * NF];
__device__ int   g_is64;
// weight blob: fp16 [n][k] images, padded strides (272B big, 80B pw1)
#define WB_WC   0
#define WB_WP2  34816
#define WB_WS   69632
#define WB_WP1  104448
#define WBLOB_BYTES 114688
__device__ unsigned char g_wb[WBLOB_BYTES];

// ===================== smem map (bytes) =====================
#define SM_WBUF0 0        // streamed weight buffer A (34816)
#define SM_WBUF1 34816    // streamed weight buffer B (34816)
#define SM_PW1   69632    // resident pw1 (10240 = 128 x 80)
#define SM_AHI   79872    // a1/chem hi (128 x 272)
#define SM_ALO   114688   // a1/chem lo
#define SM_UHI   149504   // u1 hi
#define SM_ULO   184320   // u1 lo
#define SM_PHI   149504   // posin hi (128 x 80) overlays UHI (dead before u1 written)
#define SM_PLO   159744   // posin lo
#define SM_CB1   219136
#define SM_CB2   219648
#define SM_PB1   220160
#define SM_PB2   220672
#define SM_SB    221184
#define SM_AW    221696
#define SM_ATT   222208   // 2 x 128 floats
#define SM_ROWS  223232
#define SM_COLS  223744
#define SM_AB    224256
#define SMEM_BYTES 224288

__constant__ float c_scales[15] = {
    -0.5f, -0.222222222f, -0.0987654321f, -0.0438957476f, -0.0195092212f,
    -0.00867076500f, -0.00385367333f, -0.00171274370f, -0.000761219424f,
    -0.000338319744f, -0.000150364331f, -6.68285914e-05f, -2.97015962e-05f,
    -1.32007094e-05f, -5.86698196e-06f
};

__device__ __forceinline__ float siluf(float x) {
    return __fdividef(x, 1.0f + __expf(-x));
}
__device__ __forceinline__ float sigmoidf(float x) {
    return __fdividef(1.0f, 1.0f + __expf(-x));
}
__device__ __forceinline__ uint32_t smem_u32(const void* p) {
    uint32_t a;
    asm("{ .reg .u64 t; cvta.to.shared.u64 t, %1; cvt.u32.u64 %0, t; }" : "=r"(a) : "l"(p));
    return a;
}
__device__ __forceinline__ void ldsm4(uint32_t addr, uint32_t* r) {
    asm volatile("ldmatrix.sync.aligned.m8n8.x4.shared.b16 {%0,%1,%2,%3}, [%4];"
        : "=r"(r[0]), "=r"(r[1]), "=r"(r[2]), "=r"(r[3]) : "r"(addr));
}
__device__ __forceinline__ void mma16816(float* c, const uint32_t* a, uint32_t b0, uint32_t b1) {
    asm volatile(
        "mma.sync.aligned.m16n8k16.row.col.f32.f16.f16.f32 "
        "{%0,%1,%2,%3},{%4,%5,%6,%7},{%8,%9},{%0,%1,%2,%3};"
        : "+f"(c[0]), "+f"(c[1]), "+f"(c[2]), "+f"(c[3])
        : "r"(a[0]), "r"(a[1]), "r"(a[2]), "r"(a[3]), "r"(b0), "r"(b1));
}
__device__ __forceinline__ void cp_async16(uint32_t saddr, const void* gptr) {
    asm volatile("cp.async.cg.shared.global [%0], [%1], 16;" :: "r"(saddr), "l"(gptr));
}
__device__ __forceinline__ void cp_commit() {
    asm volatile("cp.async.commit_group;" ::: "memory");
}
template<int N> __device__ __forceinline__ void cp_wait() {
    asm volatile("cp.async.wait_group %0;" :: "n"(N) : "memory");
}
// stream one 34816B weight image into smem (caller commits)
__device__ __forceinline__ void stream_weight(uint32_t sdst, const unsigned char* gsrc, int tid) {
    for (int i = tid; i < 2176; i += THREADS)
        cp_async16(sdst + i * 16, gsrc + (size_t)i * 16);
}

// 128xNx(16*nks) GEMM, warp (mw: 32 rows, nw: 64 cols), A hi/lo 2-pass with
// B fragments hoisted across passes. acc[2][8][4] f32.
__device__ __forceinline__ void gemm128(
    uint32_t aHi, uint32_t aLo, uint32_t bBase, int nks,
    int mw, int nw, int lane, float acc[2][8][4],
    uint32_t strA, uint32_t strB)
{
    const uint32_t arow = (uint32_t)(mw * 32 + (lane & 15));
    const uint32_t brow = (uint32_t)(nw * 64 + (lane & 15));
    const uint32_t kch  = (uint32_t)(lane >> 4) * 16;
    for (int ks = 0; ks < nks; ks++) {
        const uint32_t koff = kch + ks * 32;
        uint32_t bg[4][4];
#pragma unroll
        for (int g = 0; g < 4; g++)
            ldsm4(bBase + (brow + g * 16) * strB + koff, bg[g]);
        uint32_t a0[4], a1[4];
        ldsm4(aHi + arow * strA + koff, a0);
        ldsm4(aHi + (arow + 16) * strA + koff, a1);
#pragma unroll
        for (int g = 0; g < 4; g++) {
            mma16816(acc[0][2*g],   a0, bg[g][0], bg[g][2]);
            mma16816(acc[0][2*g+1], a0, bg[g][1], bg[g][3]);
            mma16816(acc[1][2*g],   a1, bg[g][0], bg[g][2]);
            mma16816(acc[1][2*g+1], a1, bg[g][1], bg[g][3]);
        }
        ldsm4(aLo + arow * strA + koff, a0);
        ldsm4(aLo + (arow + 16) * strA + koff, a1);
#pragma unroll
        for (int g = 0; g < 4; g++) {
            mma16816(acc[0][2*g],   a0, bg[g][0], bg[g][2]);
            mma16816(acc[0][2*g+1], a0, bg[g][1], bg[g][3]);
            mma16816(acc[1][2*g],   a1, bg[g][0], bg[g][2]);
            mma16816(acc[1][2*g+1], a1, bg[g][1], bg[g][3]);
        }
    }
}

// ===================== kernel 0: edge dtype detection =====================
__global__ void detect_kernel(const int* __restrict__ e32, int nprobe) {
    __shared__ int nz;
    if (threadIdx.x == 0) nz = 0;
    __syncthreads();
    int local = 0;
    for (int i = threadIdx.x; i < nprobe; i += blockDim.x)
        if (e32[2 * i + 1] != 0) local = 1;
    if (local) atomicOr(&nz, 1);
    __syncthreads();
    if (threadIdx.x == 0) g_is64 = (nz == 0) ? 1 : 0;
}

// ===================== kernel 1: fold cw1 into per-node P/Q =====================
__global__ __launch_bounds__(128) void node_pre(
    const float* __restrict__ h, const float* __restrict__ na,
    const float* __restrict__ cw1, int N)
{
    __shared__ float hs[16][128];
    __shared__ float nas[16][128];
    int n0 = blockIdx.x * 16;
    int tid = threadIdx.x;
    for (int idx = tid; idx < 16 * 128; idx += 128) {
        int n = idx >> 7, k = idx & 127;
        int gn = n0 + n;
        hs[n][k]  = (gn < N) ? h[(size_t)gn * 128 + k]  : 0.0f;
        nas[n][k] = (gn < N) ? na[(size_t)gn * 128 + k] : 0.0f;
    }
    __syncthreads();
    int j = tid;
    float accP[16], accQ[16];
#pragma unroll
    for (int n = 0; n < 16; n++) { accP[n] = 0.0f; accQ[n] = 0.0f; }
    for (int k = 0; k < 128; k++) {
        float whr = cw1[(size_t)k * 128 + j];
        float whc = cw1[(size_t)(128 + k) * 128 + j];
        float wnr = cw1[(size_t)(256 + k) * 128 + j];
        float wnc = cw1[(size_t)(384 + k) * 128 + j];
#pragma unroll
        for (int n = 0; n < 16; n++) {
            float hv = hs[n][k], nav = nas[n][k];
            accP[n] = fmaf(hv, whr, fmaf(nav, wnr, accP[n]));
            accQ[n] = fmaf(hv, whc, fmaf(nav, wnc, accQ[n]));
        }
    }
#pragma unroll
    for (int n = 0; n < 16; n++) {
        int gn = n0 + n;
        if (gn < N) {
            g_P[(size_t)gn * 128 + j] = accP[n];
            g_Q[(size_t)gn * 128 + j] = accQ[n];
        }
    }
}

// ===================== kernel 2: weight prep (transpose + fp16) =====================
__global__ void prep_weights(const float* __restrict__ cw2,
                             const float* __restrict__ pw2,
                             const float* __restrict__ sw,
                             const float* __restrict__ pw1)
{
    int idx = blockIdx.x * 256 + threadIdx.x;
    if (idx < 3 * 16384) {
        int m = idx / 16384, r = idx % 16384;
        int k = r >> 7, n = r & 127;
        const float* W = (m == 0) ? cw2 : ((m == 1) ? pw2 : sw);
        float w = W[(size_t)k * 128 + n];
        ((__half*)(g_wb + m * 34816))[n * 136 + k] = __float2half_rn(w);
    } else if (idx < 3 * 16384 + 4096) {
        int r = idx - 3 * 16384;
        int k = r >> 7, n = r & 127;   // k in 0..31
        float w = (k < 20) ? pw1[(size_t)k * 128 + n] : 0.0f;
        ((__half*)(g_wb + WB_WP1))[n * 40 + k] = __float2half_rn(w);
    }
}

// ===================== kernel 3: persistent HMMA edge kernel =====================
__global__ __launch_bounds__(THREADS) void edge_hmma_kernel(
    const float* __restrict__ coord, const float* __restrict__ nvecs,
    const float* __restrict__ cb1g,  const float* __restrict__ cb2g,
    const float* __restrict__ pb1g,  const float* __restrict__ pb2g,
    const float* __restrict__ sbg,   const float* __restrict__ awg,
    const float* __restrict__ abg,
    const void* __restrict__ edges, int E,
    float* __restrict__ out)
{
    extern __shared__ __align__(16) unsigned char smem[];
    const uint32_t sb0 = smem_u32(smem);
    const int tid = threadIdx.x;
    const int wid = tid >> 5, lane = tid & 31;
    const int mw = wid & 3;    // 32-row slice
    const int nw = wid >> 2;   // 64-col slice
    const unsigned char* gw = g_wb;

    float* cb1s = (float*)(smem + SM_CB1);
    float* cb2s = (float*)(smem + SM_CB2);
    float* pb1s = (float*)(smem + SM_PB1);
    float* pb2s = (float*)(smem + SM_PB2);
    float* sbs  = (float*)(smem + SM_SB);
    float* aws  = (float*)(smem + SM_AW);
    float* attPs= (float*)(smem + SM_ATT);
    int*   rows = (int*)(smem + SM_ROWS);
    int*   cols = (int*)(smem + SM_COLS);
    __half* PH = (__half*)(smem + SM_PHI);
    __half* PL = (__half*)(smem + SM_PLO);

    // resident pw1 + initial cw2 prefetch
    for (int i = tid; i < 10240 / 16; i += THREADS)
        cp_async16(sb0 + SM_PW1 + i * 16, gw + WB_WP1 + (size_t)i * 16);
    stream_weight(sb0 + SM_WBUF0, gw + WB_WC, tid);
    cp_commit();   // group: {pw1+cw2}

    if (tid < 128) {
        cb1s[tid] = cb1g[tid]; cb2s[tid] = cb2g[tid];
        pb1s[tid] = pb1g[tid]; pb2s[tid] = pb2g[tid];
        sbs[tid]  = sbg[tid];  aws[tid]  = awg[tid];
    }
    if (tid == 0) *(float*)(smem + SM_AB) = abg[0];
    const int is64 = g_is64;
    __syncthreads();
    const float abv = *(float*)(smem + SM_AB);

    const size_t chemO = (size_t)E * 128;
    const size_t posO  = (size_t)E * 256;
    const size_t cdO   = (size_t)E * 384;

    int p = 0;   // weight buffer parity
    const int nTiles = (E + TE - 1) / TE;
    for (int t = blockIdx.x; t < nTiles; t += gridDim.x) {
        const int base = t * TE;
        const uint32_t wA = sb0 + (p ? SM_WBUF1 : SM_WBUF0);   // cw2 then sw
        const uint32_t wB = sb0 + (p ? SM_WBUF0 : SM_WBUF1);   // pw2

        // ---- Phase A: prefetch pw2; geometry -> posin hi/lo, rows/cols, cd ----
        stream_weight(wB, gw + WB_WP2, tid);
        cp_commit();
        {
            const int e = tid & 127, g = tid >> 7;
            const int ge = base + e;
            int r = 0, c = 0;
            if (ge < E) {
                if (is64) {
                    const long long* pe = (const long long*)edges;
                    r = (int)pe[ge]; c = (int)pe[(size_t)E + ge];
                } else {
                    const int* pe = (const int*)edges;
                    r = pe[ge]; c = pe[(size_t)E + ge];
                }
            }
            if (g == 0) { rows[e] = r; cols[e] = c; }
            float dx = coord[r * 3 + 0] - coord[c * 3 + 0];
            float dy = coord[r * 3 + 1] - coord[c * 3 + 1];
            float dz = coord[r * 3 + 2] - coord[c * 3 + 2];
            float nrm = sqrtf(dx * dx + dy * dy + dz * dz);
            float inv = __fdividef(1.0f, nrm + 1e-8f);
            float cx = dx * inv, cy = dy * inv, cz = dz * inv;
            if (g == 0 && ge < E) {
                out[cdO + (size_t)ge * 3 + 0] = cx;
                out[cdO + (size_t)ge * 3 + 1] = cy;
                out[cdO + (size_t)ge * 3 + 2] = cz;
            }
            float ir = cx * cx + cy * cy + cz * cz;
            // pad cols 20..31 (zero) handled here every tile for this edge's row
            if (g == 0) {
#pragma unroll
                for (int k = 20; k < 32; k += 2) {
                    *(__half2*)(PH + e * 40 + k) = __halves2half2(__float2half_rn(0.f), __float2half_rn(0.f));
                    *(__half2*)(PL + e * 40 + k) = __halves2half2(__float2half_rn(0.f), __float2half_rn(0.f));
                }
#pragma unroll
                for (int s = 0; s < 8; s++) {
                    float v = __expf(ir * c_scales[s]);
                    __half hh = __float2half_rn(v);
                    PH[e * 40 + 5 + s] = hh;
                    PL[e * 40 + 5 + s] = __float2half_rn(v - __half2float(hh));
                }
#pragma unroll
                for (int k2 = 0; k2 < 3; k2++) {
                    const float* av = &nvecs[((size_t)r * 5 + k2) * 3];
                    const float* bv = &nvecs[((size_t)c * 5 + k2) * 3];
                    float v = av[0] * bv[0] + av[1] * bv[1] + av[2] * bv[2];
                    __half hh = __float2half_rn(v);
                    PH[e * 40 + k2] = hh;
                    PL[e * 40 + k2] = __float2half_rn(v - __half2float(hh));
                }
            } else {
#pragma unroll
                for (int s = 8; s < 15; s++) {
                    float v = __expf(ir * c_scales[s]);
                    __half hh = __float2half_rn(v);
                    PH[e * 40 + 5 + s] = hh;
                    PL[e * 40 + 5 + s] = __float2half_rn(v - __half2float(hh));
                }
#pragma unroll
                for (int k2 = 3; k2 < 5; k2++) {
                    const float* av = &nvecs[((size_t)r * 5 + k2) * 3];
                    const float* bv = &nvecs[((size_t)c * 5 + k2) * 3];
                    float v = av[0] * bv[0] + av[1] * bv[1] + av[2] * bv[2];
                    __half hh = __float2half_rn(v);
                    PH[e * 40 + k2] = hh;
                    PL[e * 40 + k2] = __float2half_rn(v - __half2float(hh));
                }
            }
        }
        __syncthreads();   // S1

        // ---- Phase B: a1 = silu(P[r]+Q[c]+cb1) -> bufA hi/lo ----
        {
            const int e = tid >> 1;
            const int k0 = (tid & 1) * 64;
            const int r = rows[e], c = cols[e];
            const float* Pr = g_P + (size_t)r * 128;
            const float* Qc = g_Q + (size_t)c * 128;
            __half2* AH = (__half2*)(smem + SM_AHI + e * 272 + k0 * 2);
            __half2* AL = (__half2*)(smem + SM_ALO + e * 272 + k0 * 2);
#pragma unroll
            for (int j = 0; j < 64; j += 2) {
                float2 pp = *(const float2*)(Pr + k0 + j);
                float2 qq = *(const float2*)(Qc + k0 + j);
                float v0 = siluf(pp.x + qq.x + cb1s[k0 + j]);
                float v1 = siluf(pp.y + qq.y + cb1s[k0 + j + 1]);
                __half h0 = __float2half_rn(v0), h1 = __float2half_rn(v1);
                AH[j >> 1] = __halves2half2(h0, h1);
                AL[j >> 1] = __halves2half2(__float2half_rn(v0 - __half2float(h0)),
                                            __float2half_rn(v1 - __half2float(h1)));
            }
        }
        cp_wait<1>();      // cw2 (and pw1) resident; pw2 may still be in flight
        __syncthreads();   // S2

        // ---- GEMM1: u1_pre = posin @ pw1 ; chem_pre = a1 @ cw2 ----
        float accU[2][8][4], accC[2][8][4];
#pragma unroll
        for (int a = 0; a < 2; a++)
#pragma unroll
            for (int b = 0; b < 8; b++)
#pragma unroll
                for (int q = 0; q < 4; q++) { accU[a][b][q] = 0.0f; accC[a][b][q] = 0.0f; }
        gemm128(sb0 + SM_PHI, sb0 + SM_PLO, sb0 + SM_PW1, 2, mw, nw, lane, accU, 80, 80);
        gemm128(sb0 + SM_AHI, sb0 + SM_ALO, wA, 8, mw, nw, lane, accC, 272, 272);
        __syncthreads();   // S3

        // ---- Epilogue A: prefetch sw; chem -> gmem+bufA; u1 -> bufU ----
        stream_weight(wA, gw + WB_WS, tid);
        cp_commit();
#pragma unroll
        for (int mi = 0; mi < 2; mi++)
#pragma unroll
            for (int ni = 0; ni < 8; ni++) {
                float* cc_ = accC[mi][ni];
                float* cu_ = accU[mi][ni];
                int rrow = mw * 32 + mi * 16 + (lane >> 2);
                int cc = nw * 64 + ni * 8 + 2 * (lane & 3);
                float v00 = siluf(cc_[0] + cb2s[cc]);
                float v01 = siluf(cc_[1] + cb2s[cc + 1]);
                float v10 = siluf(cc_[2] + cb2s[cc]);
                float v11 = siluf(cc_[3] + cb2s[cc + 1]);
                int ge0 = base + rrow, ge1 = base + rrow + 8;
                if (ge0 < E) *(float2*)(out + chemO + (size_t)ge0 * 128 + cc) = make_float2(v00, v01);
                if (ge1 < E) *(float2*)(out + chemO + (size_t)ge1 * 128 + cc) = make_float2(v10, v11);
                __half h;
                h = __float2half_rn(v00);
                *(__half2*)(smem + SM_AHI + rrow * 272 + cc * 2) = __halves2half2(h, __float2half_rn(v01));
                *(__half2*)(smem + SM_ALO + rrow * 272 + cc * 2) =
                    __halves2half2(__float2half_rn(v00 - __half2float(h)),
                                   __float2half_rn(v01 - __half2float(__float2half_rn(v01))));
                h = __float2half_rn(v10);
                *(__half2*)(smem + SM_AHI + (rrow + 8) * 272 + cc * 2) = __halves2half2(h, __float2half_rn(v11));
                *(__half2*)(smem + SM_ALO + (rrow + 8) * 272 + cc * 2) =
                    __halves2half2(__float2half_rn(v10 - __half2float(h)),
                                   __float2half_rn(v11 - __half2float(__float2half_rn(v11))));
                float u00 = siluf(cu_[0] + pb1s[cc]);
                float u01 = siluf(cu_[1] + pb1s[cc + 1]);
                float u10 = siluf(cu_[2] + pb1s[cc]);
                float u11 = siluf(cu_[3] + pb1s[cc + 1]);
                h = __float2half_rn(u00);
                *(__half2*)(smem + SM_UHI + rrow * 272 + cc * 2) = __halves2half2(h, __float2half_rn(u01));
                *(__half2*)(smem + SM_ULO + rrow * 272 + cc * 2) =
                    __halves2half2(__float2half_rn(u00 - __half2float(h)),
                                   __float2half_rn(u01 - __half2float(__float2half_rn(u01))));
                h = __float2half_rn(u10);
                *(__half2*)(smem + SM_UHI + (rrow + 8) * 272 + cc * 2) = __halves2half2(h, __float2half_rn(u11));
                *(__half2*)(smem + SM_ULO + (rrow + 8) * 272 + cc * 2) =
                    __halves2half2(__float2half_rn(u10 - __half2float(h)),
                                   __float2half_rn(u11 - __half2float(__float2half_rn(u11))));
            }
        cp_wait<0>();      // pw2 + sw resident
        __syncthreads();   // S4

        // ---- GEMM2: pos_pre = u1 @ pw2 ; gate_pre = chem @ sw ----
        float accP8[2][8][4], accG[2][8][4];
#pragma unroll
        for (int a = 0; a < 2; a++)
#pragma unroll
            for (int b = 0; b < 8; b++)
#pragma unroll
                for (int q = 0; q < 4; q++) { accP8[a][b][q] = 0.0f; accG[a][b][q] = 0.0f; }
        gemm128(sb0 + SM_UHI, sb0 + SM_ULO, wB, 8, mw, nw, lane, accP8, 272, 272);
        gemm128(sb0 + SM_AHI, sb0 + SM_ALO, wA, 8, mw, nw, lane, accG, 272, 272);

        // ---- Epilogue B part 1: pos -> gmem; gate*pos; att partials ----
        float rs[4] = {0.0f, 0.0f, 0.0f, 0.0f};
#pragma unroll
        for (int mi = 0; mi < 2; mi++)
#pragma unroll
            for (int ni = 0; ni < 8; ni++) {
                float* cp_ = accP8[mi][ni];
                float* cg = accG[mi][ni];
                int rrow = mw * 32 + mi * 16 + (lane >> 2);
                int cc = nw * 64 + ni * 8 + 2 * (lane & 3);
                float p00 = siluf(cp_[0] + pb2s[cc]);
                float p01 = siluf(cp_[1] + pb2s[cc + 1]);
                float p10 = siluf(cp_[2] + pb2s[cc]);
                float p11 = siluf(cp_[3] + pb2s[cc + 1]);
                int ge0 = base + rrow, ge1 = base + rrow + 8;
                if (ge0 < E) *(float2*)(out + posO + (size_t)ge0 * 128 + cc) = make_float2(p00, p01);
                if (ge1 < E) *(float2*)(out + posO + (size_t)ge1 * 128 + cc) = make_float2(p10, p11);
                float g00 = siluf(cg[0] + sbs[cc])     * p00;
                float g01 = siluf(cg[1] + sbs[cc + 1]) * p01;
                float g10 = siluf(cg[2] + sbs[cc])     * p10;
                float g11 = siluf(cg[3] + sbs[cc + 1]) * p11;
                cg[0] = g00; cg[1] = g01; cg[2] = g10; cg[3] = g11;
                rs[mi * 2 + 0] += g00 * aws[cc] + g01 * aws[cc + 1];
                rs[mi * 2 + 1] += g10 * aws[cc] + g11 * aws[cc + 1];
            }
#pragma unroll
        for (int s = 0; s < 4; s++) {
            rs[s] += __shfl_xor_sync(0xffffffffu, rs[s], 1);
            rs[s] += __shfl_xor_sync(0xffffffffu, rs[s], 2);
        }
        if ((lane & 3) == 0) {
#pragma unroll
            for (int s = 0; s < 4; s++) {
                int row = mw * 32 + (s >> 1) * 16 + (lane >> 2) + (s & 1) * 8;
                attPs[nw * 128 + row] = rs[s];
            }
        }
        __syncthreads();   // S5

        // ---- Epilogue B part 2: prefetch next cw2; att; final store ----
        stream_weight(wB, gw + WB_WC, tid);   // next tile's cw2 -> other buffer
        cp_commit();
        float attv[4];
#pragma unroll
        for (int s = 0; s < 4; s++) {
            int row = mw * 32 + (s >> 1) * 16 + (lane >> 2) + (s & 1) * 8;
            attv[s] = sigmoidf(attPs[row] + attPs[128 + row] + abv);
        }
#pragma unroll
        for (int mi = 0; mi < 2; mi++)
#pragma unroll
            for (int ni = 0; ni < 8; ni++) {
                float* cg = accG[mi][ni];
                int rrow = mw * 32 + mi * 16 + (lane >> 2);
                int cc = nw * 64 + ni * 8 + 2 * (lane & 3);
                int ge0 = base + rrow, ge1 = base + rrow + 8;
                float a0 = attv[mi * 2 + 0], a1 = attv[mi * 2 + 1];
                if (ge0 < E) *(float2*)(out + (size_t)ge0 * 128 + cc) =
                    make_float2(cg[0] * a0, cg[1] * a0);
                if (ge1 < E) *(float2*)(out + (size_t)ge1 * 128 + cc) =
                    make_float2(cg[2] * a1, cg[3] * a1);
            }
        p ^= 1;
    }
    cp_wait<0>();
}

// ===================== launch =====================
extern "C" void kernel_launch(void* const* d_in, const int* in_sizes, int n_in,
                              void* d_out, int out_size) {
    const float* h     = (const float*)d_in[0];
    const float* coord = (const float*)d_in[1];
    const float* nvecs = (const float*)d_in[2];
    const float* na    = (const float*)d_in[3];
    const float* cw1   = (const float*)d_in[4];
    const float* cb1   = (const float*)d_in[5];
    const float* cw2   = (const float*)d_in[6];
    const float* cb2   = (const float*)d_in[7];
    const float* pw1   = (const float*)d_in[8];
    const float* pb1   = (const float*)d_in[9];
    const float* pw2   = (const float*)d_in[10];
    const float* pb2   = (const float*)d_in[11];
    const float* sw    = (const float*)d_in[12];
    const float* sb    = (const float*)d_in[13];
    const float* aw    = (const float*)d_in[14];
    const float* ab    = (const float*)d_in[15];
    const void*  edges = d_in[16];

    const int N = in_sizes[0] / NF;
    const int E = out_size / 387;   // out, chem, pos (128 each) + cd (3)
    float* out = (float*)d_out;

    cudaFuncSetAttribute(edge_hmma_kernel,
                         cudaFuncAttributeMaxDynamicSharedMemorySize, SMEM_BYTES);

    int nprobe = (E < 1024) ? E : 1024;
    detect_kernel<<<1, 256>>>((const int*)edges, nprobe);
    prep_weights<<<(3 * 16384 + 4096 + 255) / 256, 256>>>(cw2, pw2, sw, pw1);
    node_pre<<<(N + 15) / 16, 128>>>(h, na, cw1, N);

    const int nTiles = (E + TE - 1) / TE;
    const int grid = nTiles < 148 ? nTiles : 148;
    edge_hmma_kernel<<<grid, THREADS, SMEM_BYTES>>>(
        coord, nvecs, cb1, cb2, pb1, pb2, sb, aw, ab, edges, E, out);
}

// round 12
// speedup vs baseline: 1.0145x; 1.0145x over previous
#include <cuda_runtime.h>
#include <cuda_fp16.h>
#include <stdint.h>

#define NF 128
#define NMAX 10000
#define THREADS 512
#define TE 128

// ===================== scratch =====================
__device__ float g_P[NMAX * NF];
__device__ float g_Q[NMAX * NF];
__device__ int   g_is64;
// weight blob: fp16 [n][k] images, padded strides (272B big, 80B pw1)
#define WB_WC   0
#define WB_WP2  34816
#define WB_WS   69632
#define WB_WP1  104448
#define WBLOB_BYTES 114688
__device__ unsigned char g_wb[WBLOB_BYTES];

// ===================== smem map (bytes) =====================
#define SM_WBUF0 0        // streamed weight buffer A (34816)
#define SM_WBUF1 34816    // streamed weight buffer B (34816)
#define SM_PW1   69632    // resident pw1 (10240 = 128 x 80)
#define SM_AHI   79872    // a1/chem hi (128 x 272)
#define SM_ALO   114688   // a1/chem lo
#define SM_UHI   149504   // u1 hi
#define SM_ULO   184320   // u1 lo
#define SM_PHI   149504   // posin hi (128 x 80) overlays UHI (dead before u1 written)
#define SM_PLO   159744   // posin lo
#define SM_CB1   219136
#define SM_CB2   219648
#define SM_PB1   220160
#define SM_PB2   220672
#define SM_SB    221184
#define SM_AW    221696
#define SM_ATT   222208   // 2 x 128 floats
#define SM_ROWS  223232
#define SM_COLS  223744
#define SM_AB    224256
#define SMEM_BYTES 224288

__constant__ float c_scales[15] = {
    -0.5f, -0.222222222f, -0.0987654321f, -0.0438957476f, -0.0195092212f,
    -0.00867076500f, -0.00385367333f, -0.00171274370f, -0.000761219424f,
    -0.000338319744f, -0.000150364331f, -6.68285914e-05f, -2.97015962e-05f,
    -1.32007094e-05f, -5.86698196e-06f
};

__device__ __forceinline__ float siluf(float x) {
    return __fdividef(x, 1.0f + __expf(-x));
}
__device__ __forceinline__ float sigmoidf(float x) {
    return __fdividef(1.0f, 1.0f + __expf(-x));
}
__device__ __forceinline__ uint32_t smem_u32(const void* p) {
    uint32_t a;
    asm("{ .reg .u64 t; cvta.to.shared.u64 t, %1; cvt.u32.u64 %0, t; }" : "=r"(a) : "l"(p));
    return a;
}
__device__ __forceinline__ void ldsm4(uint32_t addr, uint32_t* r) {
    asm volatile("ldmatrix.sync.aligned.m8n8.x4.shared.b16 {%0,%1,%2,%3}, [%4];"
        : "=r"(r[0]), "=r"(r[1]), "=r"(r[2]), "=r"(r[3]) : "r"(addr));
}
__device__ __forceinline__ void mma16816(float* c, const uint32_t* a, uint32_t b0, uint32_t b1) {
    asm volatile(
        "mma.sync.aligned.m16n8k16.row.col.f32.f16.f16.f32 "
        "{%0,%1,%2,%3},{%4,%5,%6,%7},{%8,%9},{%0,%1,%2,%3};"
        : "+f"(c[0]), "+f"(c[1]), "+f"(c[2]), "+f"(c[3])
        : "r"(a[0]), "r"(a[1]), "r"(a[2]), "r"(a[3]), "r"(b0), "r"(b1));
}
__device__ __forceinline__ void cp_async16(uint32_t saddr, const void* gptr) {
    asm volatile("cp.async.cg.shared.global [%0], [%1], 16;" :: "r"(saddr), "l"(gptr));
}
__device__ __forceinline__ void cp_commit() {
    asm volatile("cp.async.commit_group;" ::: "memory");
}
template<int N> __device__ __forceinline__ void cp_wait() {
    asm volatile("cp.async.wait_group %0;" :: "n"(N) : "memory");
}
// stream one 34816B weight image into smem (caller commits)
__device__ __forceinline__ void stream_weight(uint32_t sdst, const unsigned char* gsrc, int tid) {
    for (int i = tid; i < 2176; i += THREADS)
        cp_async16(sdst + i * 16, gsrc + (size_t)i * 16);
}

// 128xNx(16*nks) GEMM, 16 warps: warp (mw: 16 rows, nw: 64 cols).
// A hi/lo 2-pass with B fragments hoisted. acc[8][4] f32.
__device__ __forceinline__ void gemm128(
    uint32_t aHi, uint32_t aLo, uint32_t bBase, int nks,
    int mw, int nw, int lane, float acc[8][4],
    uint32_t strA, uint32_t strB)
{
    const uint32_t arow = (uint32_t)(mw * 16 + (lane & 15));
    const uint32_t brow = (uint32_t)(nw * 64 + (lane & 15));
    const uint32_t kch  = (uint32_t)(lane >> 4) * 16;
    for (int ks = 0; ks < nks; ks++) {
        const uint32_t koff = kch + ks * 32;
        uint32_t bg[4][4];
#pragma unroll
        for (int g = 0; g < 4; g++)
            ldsm4(bBase + (brow + g * 16) * strB + koff, bg[g]);
        uint32_t a0[4];
        ldsm4(aHi + arow * strA + koff, a0);
#pragma unroll
        for (int g = 0; g < 4; g++) {
            mma16816(acc[2*g],   a0, bg[g][0], bg[g][2]);
            mma16816(acc[2*g+1], a0, bg[g][1], bg[g][3]);
        }
        ldsm4(aLo + arow * strA + koff, a0);
#pragma unroll
        for (int g = 0; g < 4; g++) {
            mma16816(acc[2*g],   a0, bg[g][0], bg[g][2]);
            mma16816(acc[2*g+1], a0, bg[g][1], bg[g][3]);
        }
    }
}

// ===================== kernel 0: edge dtype detection =====================
__global__ void detect_kernel(const int* __restrict__ e32, int nprobe) {
    __shared__ int nz;
    if (threadIdx.x == 0) nz = 0;
    __syncthreads();
    int local = 0;
    for (int i = threadIdx.x; i < nprobe; i += blockDim.x)
        if (e32[2 * i + 1] != 0) local = 1;
    if (local) atomicOr(&nz, 1);
    __syncthreads();
    if (threadIdx.x == 0) g_is64 = (nz == 0) ? 1 : 0;
}

// ===================== kernel 1: fold cw1 into per-node P/Q =====================
__global__ __launch_bounds__(128) void node_pre(
    const float* __restrict__ h, const float* __restrict__ na,
    const float* __restrict__ cw1, int N)
{
    __shared__ float hs[16][128];
    __shared__ float nas[16][128];
    int n0 = blockIdx.x * 16;
    int tid = threadIdx.x;
    for (int idx = tid; idx < 16 * 128; idx += 128) {
        int n = idx >> 7, k = idx & 127;
        int gn = n0 + n;
        hs[n][k]  = (gn < N) ? h[(size_t)gn * 128 + k]  : 0.0f;
        nas[n][k] = (gn < N) ? na[(size_t)gn * 128 + k] : 0.0f;
    }
    __syncthreads();
    int j = tid;
    float accP[16], accQ[16];
#pragma unroll
    for (int n = 0; n < 16; n++) { accP[n] = 0.0f; accQ[n] = 0.0f; }
    for (int k = 0; k < 128; k++) {
        float whr = cw1[(size_t)k * 128 + j];
        float whc = cw1[(size_t)(128 + k) * 128 + j];
        float wnr = cw1[(size_t)(256 + k) * 128 + j];
        float wnc = cw1[(size_t)(384 + k) * 128 + j];
#pragma unroll
        for (int n = 0; n < 16; n++) {
            float hv = hs[n][k], nav = nas[n][k];
            accP[n] = fmaf(hv, whr, fmaf(nav, wnr, accP[n]));
            accQ[n] = fmaf(hv, whc, fmaf(nav, wnc, accQ[n]));
        }
    }
#pragma unroll
    for (int n = 0; n < 16; n++) {
        int gn = n0 + n;
        if (gn < N) {
            g_P[(size_t)gn * 128 + j] = accP[n];
            g_Q[(size_t)gn * 128 + j] = accQ[n];
        }
    }
}

// ===================== kernel 2: weight prep (transpose + fp16) =====================
__global__ void prep_weights(const float* __restrict__ cw2,
                             const float* __restrict__ pw2,
                             const float* __restrict__ sw,
                             const float* __restrict__ pw1)
{
    int idx = blockIdx.x * 256 + threadIdx.x;
    if (idx < 3 * 16384) {
        int m = idx / 16384, r = idx % 16384;
        int k = r >> 7, n = r & 127;
        const float* W = (m == 0) ? cw2 : ((m == 1) ? pw2 : sw);
        float w = W[(size_t)k * 128 + n];
        ((__half*)(g_wb + m * 34816))[n * 136 + k] = __float2half_rn(w);
    } else if (idx < 3 * 16384 + 4096) {
        int r = idx - 3 * 16384;
        int k = r >> 7, n = r & 127;   // k in 0..31
        float w = (k < 20) ? pw1[(size_t)k * 128 + n] : 0.0f;
        ((__half*)(g_wb + WB_WP1))[n * 40 + k] = __float2half_rn(w);
    }
}

// ===================== kernel 3: persistent HMMA edge kernel =====================
__global__ __launch_bounds__(THREADS) void edge_hmma_kernel(
    const float* __restrict__ coord, const float* __restrict__ nvecs,
    const float* __restrict__ cb1g,  const float* __restrict__ cb2g,
    const float* __restrict__ pb1g,  const float* __restrict__ pb2g,
    const float* __restrict__ sbg,   const float* __restrict__ awg,
    const float* __restrict__ abg,
    const void* __restrict__ edges, int E,
    float* __restrict__ out)
{
    extern __shared__ __align__(16) unsigned char smem[];
    const uint32_t sb0 = smem_u32(smem);
    const int tid = threadIdx.x;
    const int wid = tid >> 5, lane = tid & 31;
    const int mw = wid & 7;    // 16-row slice
    const int nw = wid >> 3;   // 64-col slice
    const unsigned char* gw = g_wb;

    float* cb1s = (float*)(smem + SM_CB1);
    float* cb2s = (float*)(smem + SM_CB2);
    float* pb1s = (float*)(smem + SM_PB1);
    float* pb2s = (float*)(smem + SM_PB2);
    float* sbs  = (float*)(smem + SM_SB);
    float* aws  = (float*)(smem + SM_AW);
    float* attPs= (float*)(smem + SM_ATT);
    int*   rows = (int*)(smem + SM_ROWS);
    int*   cols = (int*)(smem + SM_COLS);
    __half* PH = (__half*)(smem + SM_PHI);
    __half* PL = (__half*)(smem + SM_PLO);

    // resident pw1 + initial cw2 prefetch
    for (int i = tid; i < 10240 / 16; i += THREADS)
        cp_async16(sb0 + SM_PW1 + i * 16, gw + WB_WP1 + (size_t)i * 16);
    stream_weight(sb0 + SM_WBUF0, gw + WB_WC, tid);
    cp_commit();   // group: {pw1+cw2}

    if (tid < 128) {
        cb1s[tid] = cb1g[tid]; cb2s[tid] = cb2g[tid];
        pb1s[tid] = pb1g[tid]; pb2s[tid] = pb2g[tid];
        sbs[tid]  = sbg[tid];  aws[tid]  = awg[tid];
    }
    if (tid == 0) *(float*)(smem + SM_AB) = abg[0];
    const int is64 = g_is64;
    __syncthreads();
    const float abv = *(float*)(smem + SM_AB);

    const size_t chemO = (size_t)E * 128;
    const size_t posO  = (size_t)E * 256;
    const size_t cdO   = (size_t)E * 384;

    int p = 0;   // weight buffer parity
    const int nTiles = (E + TE - 1) / TE;
    for (int t = blockIdx.x; t < nTiles; t += gridDim.x) {
        const int base = t * TE;
        const uint32_t wA = sb0 + (p ? SM_WBUF1 : SM_WBUF0);   // cw2 then sw
        const uint32_t wB = sb0 + (p ? SM_WBUF0 : SM_WBUF1);   // pw2

        // ---- Phase A: prefetch pw2; geometry -> posin hi/lo, rows/cols, cd ----
        stream_weight(wB, gw + WB_WP2, tid);
        cp_commit();
        {
            const int e = tid & 127, g = tid >> 7;   // g in 0..3
            const int ge = base + e;
            int r = 0, c = 0;
            if (ge < E) {
                if (is64) {
                    const long long* pe = (const long long*)edges;
                    r = (int)pe[ge]; c = (int)pe[(size_t)E + ge];
                } else {
                    const int* pe = (const int*)edges;
                    r = pe[ge]; c = pe[(size_t)E + ge];
                }
            }
            if (g == 0) { rows[e] = r; cols[e] = c; }
            float dx = coord[r * 3 + 0] - coord[c * 3 + 0];
            float dy = coord[r * 3 + 1] - coord[c * 3 + 1];
            float dz = coord[r * 3 + 2] - coord[c * 3 + 2];
            float nrm = sqrtf(dx * dx + dy * dy + dz * dz);
            float inv = __fdividef(1.0f, nrm + 1e-8f);
            float cx = dx * inv, cy = dy * inv, cz = dz * inv;
            if (g == 0 && ge < E) {
                out[cdO + (size_t)ge * 3 + 0] = cx;
                out[cdO + (size_t)ge * 3 + 1] = cy;
                out[cdO + (size_t)ge * 3 + 2] = cz;
            }
            float ir = cx * cx + cy * cy + cz * cz;
            if (g == 0) {
#pragma unroll
                for (int k = 20; k < 32; k += 2) {
                    *(__half2*)(PH + e * 40 + k) = __halves2half2(__float2half_rn(0.f), __float2half_rn(0.f));
                    *(__half2*)(PL + e * 40 + k) = __halves2half2(__float2half_rn(0.f), __float2half_rn(0.f));
                }
            }
            // exps: group g covers indices [4g, min(4g+4,15))
#pragma unroll
            for (int s = 0; s < 4; s++) {
                int si = g * 4 + s;
                if (si < 15) {
                    float v = __expf(ir * c_scales[si]);
                    __half hh = __float2half_rn(v);
                    PH[e * 40 + 5 + si] = hh;
                    PL[e * 40 + 5 + si] = __float2half_rn(v - __half2float(hh));
                }
            }
            // nprod: group g does k2=g; group 3 also k2=4
            {
                int k2 = g;
                const float* av = &nvecs[((size_t)r * 5 + k2) * 3];
                const float* bv = &nvecs[((size_t)c * 5 + k2) * 3];
                float v = av[0] * bv[0] + av[1] * bv[1] + av[2] * bv[2];
                __half hh = __float2half_rn(v);
                PH[e * 40 + k2] = hh;
                PL[e * 40 + k2] = __float2half_rn(v - __half2float(hh));
            }
            if (g == 3) {
                const float* av = &nvecs[((size_t)r * 5 + 4) * 3];
                const float* bv = &nvecs[((size_t)c * 5 + 4) * 3];
                float v = av[0] * bv[0] + av[1] * bv[1] + av[2] * bv[2];
                __half hh = __float2half_rn(v);
                PH[e * 40 + 4] = hh;
                PL[e * 40 + 4] = __float2half_rn(v - __half2float(hh));
            }
        }
        __syncthreads();   // S1

        // ---- Phase B: a1 = silu(P[r]+Q[c]+cb1) -> bufA hi/lo ----
        {
            const int e = tid >> 2;
            const int k0 = (tid & 3) * 32;
            const int r = rows[e], c = cols[e];
            const float* Pr = g_P + (size_t)r * 128;
            const float* Qc = g_Q + (size_t)c * 128;
            __half2* AH = (__half2*)(smem + SM_AHI + e * 272 + k0 * 2);
            __half2* AL = (__half2*)(smem + SM_ALO + e * 272 + k0 * 2);
#pragma unroll
            for (int j = 0; j < 32; j += 2) {
                float2 pp = *(const float2*)(Pr + k0 + j);
                float2 qq = *(const float2*)(Qc + k0 + j);
                float v0 = siluf(pp.x + qq.x + cb1s[k0 + j]);
                float v1 = siluf(pp.y + qq.y + cb1s[k0 + j + 1]);
                __half h0 = __float2half_rn(v0), h1 = __float2half_rn(v1);
                AH[j >> 1] = __halves2half2(h0, h1);
                AL[j >> 1] = __halves2half2(__float2half_rn(v0 - __half2float(h0)),
                                            __float2half_rn(v1 - __half2float(h1)));
            }
        }
        cp_wait<1>();      // cw2 (and pw1) resident; pw2 may still be in flight
        __syncthreads();   // S2

        // ---- GEMM1: u1_pre = posin @ pw1 ; chem_pre = a1 @ cw2 ----
        float accU[8][4], accC[8][4];
#pragma unroll
        for (int b = 0; b < 8; b++)
#pragma unroll
            for (int q = 0; q < 4; q++) { accU[b][q] = 0.0f; accC[b][q] = 0.0f; }
        gemm128(sb0 + SM_PHI, sb0 + SM_PLO, sb0 + SM_PW1, 2, mw, nw, lane, accU, 80, 80);
        gemm128(sb0 + SM_AHI, sb0 + SM_ALO, wA, 8, mw, nw, lane, accC, 272, 272);
        __syncthreads();   // S3

        // ---- Epilogue A: prefetch sw; chem -> gmem+bufA; u1 -> bufU ----
        stream_weight(wA, gw + WB_WS, tid);
        cp_commit();
#pragma unroll
        for (int ni = 0; ni < 8; ni++) {
            float* cc_ = accC[ni];
            float* cu_ = accU[ni];
            int rrow = mw * 16 + (lane >> 2);
            int cc = nw * 64 + ni * 8 + 2 * (lane & 3);
            float v00 = siluf(cc_[0] + cb2s[cc]);
            float v01 = siluf(cc_[1] + cb2s[cc + 1]);
            float v10 = siluf(cc_[2] + cb2s[cc]);
            float v11 = siluf(cc_[3] + cb2s[cc + 1]);
            int ge0 = base + rrow, ge1 = base + rrow + 8;
            if (ge0 < E) *(float2*)(out + chemO + (size_t)ge0 * 128 + cc) = make_float2(v00, v01);
            if (ge1 < E) *(float2*)(out + chemO + (size_t)ge1 * 128 + cc) = make_float2(v10, v11);
            __half h;
            h = __float2half_rn(v00);
            *(__half2*)(smem + SM_AHI + rrow * 272 + cc * 2) = __halves2half2(h, __float2half_rn(v01));
            *(__half2*)(smem + SM_ALO + rrow * 272 + cc * 2) =
                __halves2half2(__float2half_rn(v00 - __half2float(h)),
                               __float2half_rn(v01 - __half2float(__float2half_rn(v01))));
            h = __float2half_rn(v10);
            *(__half2*)(smem + SM_AHI + (rrow + 8) * 272 + cc * 2) = __halves2half2(h, __float2half_rn(v11));
            *(__half2*)(smem + SM_ALO + (rrow + 8) * 272 + cc * 2) =
                __halves2half2(__float2half_rn(v10 - __half2float(h)),
                               __float2half_rn(v11 - __half2float(__float2half_rn(v11))));
            float u00 = siluf(cu_[0] + pb1s[cc]);
            float u01 = siluf(cu_[1] + pb1s[cc + 1]);
            float u10 = siluf(cu_[2] + pb1s[cc]);
            float u11 = siluf(cu_[3] + pb1s[cc + 1]);
            h = __float2half_rn(u00);
            *(__half2*)(smem + SM_UHI + rrow * 272 + cc * 2) = __halves2half2(h, __float2half_rn(u01));
            *(__half2*)(smem + SM_ULO + rrow * 272 + cc * 2) =
                __halves2half2(__float2half_rn(u00 - __half2float(h)),
                               __float2half_rn(u01 - __half2float(__float2half_rn(u01))));
            h = __float2half_rn(u10);
            *(__half2*)(smem + SM_UHI + (rrow + 8) * 272 + cc * 2) = __halves2half2(h, __float2half_rn(u11));
            *(__half2*)(smem + SM_ULO + (rrow + 8) * 272 + cc * 2) =
                __halves2half2(__float2half_rn(u10 - __half2float(h)),
                               __float2half_rn(u11 - __half2float(__float2half_rn(u11))));
        }
        cp_wait<0>();      // pw2 + sw resident
        __syncthreads();   // S4

        // ---- GEMM2: pos_pre = u1 @ pw2 ; gate_pre = chem @ sw ----
        float accP8[8][4], accG[8][4];
#pragma unroll
        for (int b = 0; b < 8; b++)
#pragma unroll
            for (int q = 0; q < 4; q++) { accP8[b][q] = 0.0f; accG[b][q] = 0.0f; }
        gemm128(sb0 + SM_UHI, sb0 + SM_ULO, wB, 8, mw, nw, lane, accP8, 272, 272);
        gemm128(sb0 + SM_AHI, sb0 + SM_ALO, wA, 8, mw, nw, lane, accG, 272, 272);

        // ---- Epilogue B part 1: pos -> gmem; gate*pos; att partials ----
        float rs0 = 0.0f, rs1 = 0.0f;
#pragma unroll
        for (int ni = 0; ni < 8; ni++) {
            float* cp_ = accP8[ni];
            float* cg = accG[ni];
            int rrow = mw * 16 + (lane >> 2);
            int cc = nw * 64 + ni * 8 + 2 * (lane & 3);
            float p00 = siluf(cp_[0] + pb2s[cc]);
            float p01 = siluf(cp_[1] + pb2s[cc + 1]);
            float p10 = siluf(cp_[2] + pb2s[cc]);
            float p11 = siluf(cp_[3] + pb2s[cc + 1]);
            int ge0 = base + rrow, ge1 = base + rrow + 8;
            if (ge0 < E) *(float2*)(out + posO + (size_t)ge0 * 128 + cc) = make_float2(p00, p01);
            if (ge1 < E) *(float2*)(out + posO + (size_t)ge1 * 128 + cc) = make_float2(p10, p11);
            float g00 = siluf(cg[0] + sbs[cc])     * p00;
            float g01 = siluf(cg[1] + sbs[cc + 1]) * p01;
            float g10 = siluf(cg[2] + sbs[cc])     * p10;
            float g11 = siluf(cg[3] + sbs[cc + 1]) * p11;
            cg[0] = g00; cg[1] = g01; cg[2] = g10; cg[3] = g11;
            rs0 += g00 * aws[cc] + g01 * aws[cc + 1];
            rs1 += g10 * aws[cc] + g11 * aws[cc + 1];
        }
        rs0 += __shfl_xor_sync(0xffffffffu, rs0, 1);
        rs0 += __shfl_xor_sync(0xffffffffu, rs0, 2);
        rs1 += __shfl_xor_sync(0xffffffffu, rs1, 1);
        rs1 += __shfl_xor_sync(0xffffffffu, rs1, 2);
        if ((lane & 3) == 0) {
            int row = mw * 16 + (lane >> 2);
            attPs[nw * 128 + row] = rs0;
            attPs[nw * 128 + row + 8] = rs1;
        }
        __syncthreads();   // S5

        // ---- Epilogue B part 2: prefetch next cw2; att; final store ----
        stream_weight(wB, gw + WB_WC, tid);   // next tile's cw2 -> other buffer
        cp_commit();
        int row0 = mw * 16 + (lane >> 2);
        float att0 = sigmoidf(attPs[row0] + attPs[128 + row0] + abv);
        float att1 = sigmoidf(attPs[row0 + 8] + attPs[128 + row0 + 8] + abv);
#pragma unroll
        for (int ni = 0; ni < 8; ni++) {
            float* cg = accG[ni];
            int cc = nw * 64 + ni * 8 + 2 * (lane & 3);
            int ge0 = base + row0, ge1 = base + row0 + 8;
            if (ge0 < E) *(float2*)(out + (size_t)ge0 * 128 + cc) =
                make_float2(cg[0] * att0, cg[1] * att0);
            if (ge1 < E) *(float2*)(out + (size_t)ge1 * 128 + cc) =
                make_float2(cg[2] * att1, cg[3] * att1);
        }
        p ^= 1;
    }
    cp_wait<0>();
}

// ===================== launch =====================
extern "C" void kernel_launch(void* const* d_in, const int* in_sizes, int n_in,
                              void* d_out, int out_size) {
    const float* h     = (const float*)d_in[0];
    const float* coord = (const float*)d_in[1];
    const float* nvecs = (const float*)d_in[2];
    const float* na    = (const float*)d_in[3];
    const float* cw1   = (const float*)d_in[4];
    const float* cb1   = (const float*)d_in[5];
    const float* cw2   = (const float*)d_in[6];
    const float* cb2   = (const float*)d_in[7];
    const float* pw1   = (const float*)d_in[8];
    const float* pb1   = (const float*)d_in[9];
    const float* pw2   = (const float*)d_in[10];
    const float* pb2   = (const float*)d_in[11];
    const float* sw    = (const float*)d_in[12];
    const float* sb    = (const float*)d_in[13];
    const float* aw    = (const float*)d_in[14];
    const float* ab    = (const float*)d_in[15];
    const void*  edges = d_in[16];

    const int N = in_sizes[0] / NF;
    const int E = out_size / 387;   // out, chem, pos (128 each) + cd (3)
    float* out = (float*)d_out;

    cudaFuncSetAttribute(edge_hmma_kernel,
                         cudaFuncAttributeMaxDynamicSharedMemorySize, SMEM_BYTES);

    int nprobe = (E < 1024) ? E : 1024;
    detect_kernel<<<1, 256>>>((const int*)edges, nprobe);
    prep_weights<<<(3 * 16384 + 4096 + 255) / 256, 256>>>(cw2, pw2, sw, pw1);
    node_pre<<<(N + 15) / 16, 128>>>(h, na, cw1, N);

    const int nTiles = (E + TE - 1) / TE;
    const int grid = nTiles < 148 ? nTiles : 148;
    edge_hmma_kernel<<<grid, THREADS, SMEM_BYTES>>>(
        coord, nvecs, cb1, cb2, pb1, pb2, sb, aw, ab, edges, E, out);
}

// round 14
// speedup vs baseline: 1.3057x; 1.2870x over previous
#include <cuda_runtime.h>
#include <cuda_fp16.h>
#include <stdint.h>

#define NF 128
#define NMAX 10000
#define THREADS 512
#define TE 64

// ===================== scratch =====================
__device__ float g_P[NMAX * NF];
__device__ float g_Q[NMAX * NF];
__device__ int   g_is64;
// weight blob: fp16 [n][k] images, padded strides (272B big, 80B pw1)
#define WB_WC   0
#define WB_WP2  34816
#define WB_WS   69632
#define WB_WP1  104448
#define WBLOB_BYTES 114688
__device__ unsigned char g_wb[WBLOB_BYTES];

// ===================== smem map (bytes) =====================
// Weights resident at the SAME offsets as the blob (single wholesale copy).
#define SM_WC    0
#define SM_WP2   34816
#define SM_WS    69632
#define SM_PW1   104448
#define SM_AHI   114688   // a1/chem hi (64 x 272)
#define SM_ALO   132096   // a1/chem lo
#define SM_UHI   149504   // u1 hi (64 x 272)
#define SM_ULO   166912   // u1 lo
#define SM_PHI   149504   // posin hi (64 x 80) overlays UHI (dead before u1 written)
#define SM_PLO   154624   // posin lo (64 x 80)
#define SM_CB1   184320
#define SM_CB2   184832
#define SM_PB1   185344
#define SM_PB2   185856
#define SM_SB    186368
#define SM_AW    186880
#define SM_ATT   187392   // 4 x 64 floats
#define SM_ROWS  188416   // 64 ints
#define SM_COLS  188672   // 64 ints
#define SM_AB    188928
#define SMEM_BYTES 188944

__constant__ float c_scales[15] = {
    -0.5f, -0.222222222f, -0.0987654321f, -0.0438957476f, -0.0195092212f,
    -0.00867076500f, -0.00385367333f, -0.00171274370f, -0.000761219424f,
    -0.000338319744f, -0.000150364331f, -6.68285914e-05f, -2.97015962e-05f,
    -1.32007094e-05f, -5.86698196e-06f
};

__device__ __forceinline__ float siluf(float x) {
    return __fdividef(x, 1.0f + __expf(-x));
}
__device__ __forceinline__ float sigmoidf(float x) {
    return __fdividef(1.0f, 1.0f + __expf(-x));
}
__device__ __forceinline__ uint32_t smem_u32(const void* p) {
    uint32_t a;
    asm("{ .reg .u64 t; cvta.to.shared.u64 t, %1; cvt.u32.u64 %0, t; }" : "=r"(a) : "l"(p));
    return a;
}
__device__ __forceinline__ void ldsm4(uint32_t addr, uint32_t* r) {
    asm volatile("ldmatrix.sync.aligned.m8n8.x4.shared.b16 {%0,%1,%2,%3}, [%4];"
        : "=r"(r[0]), "=r"(r[1]), "=r"(r[2]), "=r"(r[3]) : "r"(addr));
}
__device__ __forceinline__ void mma16816(float* c, const uint32_t* a, uint32_t b0, uint32_t b1) {
    asm volatile(
        "mma.sync.aligned.m16n8k16.row.col.f32.f16.f16.f32 "
        "{%0,%1,%2,%3},{%4,%5,%6,%7},{%8,%9},{%0,%1,%2,%3};"
        : "+f"(c[0]), "+f"(c[1]), "+f"(c[2]), "+f"(c[3])
        : "r"(a[0]), "r"(a[1]), "r"(a[2]), "r"(a[3]), "r"(b0), "r"(b1));
}

// 64xNx(16*nks) GEMM, 16 warps: warp (mw: 16 rows, nw: 32 cols).
// A hi/lo 2-pass with B fragments hoisted across passes. acc[4][4] f32.
__device__ __forceinline__ void gemm64(
    uint32_t aHi, uint32_t aLo, uint32_t bBase, int nks,
    int mw, int nw, int lane, float acc[4][4],
    uint32_t strA, uint32_t strB)
{
    const uint32_t arow = (uint32_t)(mw * 16 + (lane & 15));
    const uint32_t brow = (uint32_t)(nw * 32 + (lane & 15));
    const uint32_t kch  = (uint32_t)(lane >> 4) * 16;
    for (int ks = 0; ks < nks; ks++) {
        const uint32_t koff = kch + ks * 32;
        uint32_t b0[4], b1[4], a[4];
        ldsm4(bBase + brow * strB + koff, b0);
        ldsm4(bBase + (brow + 16) * strB + koff, b1);
        ldsm4(aHi + arow * strA + koff, a);
        mma16816(acc[0], a, b0[0], b0[2]);
        mma16816(acc[1], a, b0[1], b0[3]);
        mma16816(acc[2], a, b1[0], b1[2]);
        mma16816(acc[3], a, b1[1], b1[3]);
        ldsm4(aLo + arow * strA + koff, a);
        mma16816(acc[0], a, b0[0], b0[2]);
        mma16816(acc[1], a, b0[1], b0[3]);
        mma16816(acc[2], a, b1[0], b1[2]);
        mma16816(acc[3], a, b1[1], b1[3]);
    }
}

// ===================== kernel 0: edge dtype detection =====================
__global__ void detect_kernel(const int* __restrict__ e32, int nprobe) {
    __shared__ int nz;
    if (threadIdx.x == 0) nz = 0;
    __syncthreads();
    int local = 0;
    for (int i = threadIdx.x; i < nprobe; i += blockDim.x)
        if (e32[2 * i + 1] != 0) local = 1;
    if (local) atomicOr(&nz, 1);
    __syncthreads();
    if (threadIdx.x == 0) g_is64 = (nz == 0) ? 1 : 0;
}

// ===================== kernel 1: fold cw1 into per-node P/Q =====================
__global__ __launch_bounds__(128) void node_pre(
    const float* __restrict__ h, const float* __restrict__ na,
    const float* __restrict__ cw1, int N)
{
    __shared__ float hs[16][128];
    __shared__ float nas[16][128];
    int n0 = blockIdx.x * 16;
    int tid = threadIdx.x;
    for (int idx = tid; idx < 16 * 128; idx += 128) {
        int n = idx >> 7, k = idx & 127;
        int gn = n0 + n;
        hs[n][k]  = (gn < N) ? h[(size_t)gn * 128 + k]  : 0.0f;
        nas[n][k] = (gn < N) ? na[(size_t)gn * 128 + k] : 0.0f;
    }
    __syncthreads();
    int j = tid;
    float accP[16], accQ[16];
#pragma unroll
    for (int n = 0; n < 16; n++) { accP[n] = 0.0f; accQ[n] = 0.0f; }
    for (int k = 0; k < 128; k++) {
        float whr = cw1[(size_t)k * 128 + j];
        float whc = cw1[(size_t)(128 + k) * 128 + j];
        float wnr = cw1[(size_t)(256 + k) * 128 + j];
        float wnc = cw1[(size_t)(384 + k) * 128 + j];
#pragma unroll
        for (int n = 0; n < 16; n++) {
            float hv = hs[n][k], nav = nas[n][k];
            accP[n] = fmaf(hv, whr, fmaf(nav, wnr, accP[n]));
            accQ[n] = fmaf(hv, whc, fmaf(nav, wnc, accQ[n]));
        }
    }
#pragma unroll
    for (int n = 0; n < 16; n++) {
        int gn = n0 + n;
        if (gn < N) {
            g_P[(size_t)gn * 128 + j] = accP[n];
            g_Q[(size_t)gn * 128 + j] = accQ[n];
        }
    }
}

// ===================== kernel 2: weight prep (transpose + fp16) =====================
__global__ void prep_weights(const float* __restrict__ cw2,
                             const float* __restrict__ pw2,
                             const float* __restrict__ sw,
                             const float* __restrict__ pw1)
{
    int idx = blockIdx.x * 256 + threadIdx.x;
    if (idx < 3 * 16384) {
        int m = idx / 16384, r = idx % 16384;
        int k = r >> 7, n = r & 127;
        const float* W = (m == 0) ? cw2 : ((m == 1) ? pw2 : sw);
        float w = W[(size_t)k * 128 + n];
        ((__half*)(g_wb + m * 34816))[n * 136 + k] = __float2half_rn(w);
    } else if (idx < 3 * 16384 + 4096) {
        int r = idx - 3 * 16384;
        int k = r >> 7, n = r & 127;   // k in 0..31
        float w = (k < 20) ? pw1[(size_t)k * 128 + n] : 0.0f;
        ((__half*)(g_wb + WB_WP1))[n * 40 + k] = __float2half_rn(w);
    }
}

// ===================== kernel 3: persistent HMMA edge kernel =====================
__global__ __launch_bounds__(THREADS) void edge_hmma_kernel(
    const float* __restrict__ coord, const float* __restrict__ nvecs,
    const float* __restrict__ cb1g,  const float* __restrict__ cb2g,
    const float* __restrict__ pb1g,  const float* __restrict__ pb2g,
    const float* __restrict__ sbg,   const float* __restrict__ awg,
    const float* __restrict__ abg,
    const void* __restrict__ edges, int E,
    float* __restrict__ out)
{
    extern __shared__ __align__(16) unsigned char smem[];
    const uint32_t sb0 = smem_u32(smem);
    const int tid = threadIdx.x;
    const int wid = tid >> 5, lane = tid & 31;
    const int mw = wid & 3;    // 16-row slice
    const int nw = wid >> 2;   // 32-col slice

    // weight blob -> smem (one-time, offsets identical)
    {
        const uint4* src = (const uint4*)g_wb;
        uint4* dst = (uint4*)smem;
        for (int i = tid; i < WBLOB_BYTES / 16; i += THREADS) dst[i] = src[i];
    }
    float* cb1s = (float*)(smem + SM_CB1);
    float* cb2s = (float*)(smem + SM_CB2);
    float* pb1s = (float*)(smem + SM_PB1);
    float* pb2s = (float*)(smem + SM_PB2);
    float* sbs  = (float*)(smem + SM_SB);
    float* aws  = (float*)(smem + SM_AW);
    float* attPs= (float*)(smem + SM_ATT);
    int*   rows = (int*)(smem + SM_ROWS);
    int*   cols = (int*)(smem + SM_COLS);
    __half* PH = (__half*)(smem + SM_PHI);
    __half* PL = (__half*)(smem + SM_PLO);
    if (tid < 128) {
        cb1s[tid] = cb1g[tid]; cb2s[tid] = cb2g[tid];
        pb1s[tid] = pb1g[tid]; pb2s[tid] = pb2g[tid];
        sbs[tid]  = sbg[tid];  aws[tid]  = awg[tid];
    }
    if (tid == 0) *(float*)(smem + SM_AB) = abg[0];
    const int is64 = g_is64;
    __syncthreads();
    const float abv = *(float*)(smem + SM_AB);

    const size_t chemO = (size_t)E * 128;
    const size_t posO  = (size_t)E * 256;
    const size_t cdO   = (size_t)E * 384;

    const int nTiles = (E + TE - 1) / TE;
    for (int t = blockIdx.x; t < nTiles; t += gridDim.x) {
        const int base = t * TE;

        // ---- Phase A: geometry -> posin hi/lo (8 threads per edge) ----
        {
            const int e = tid & 63, g = tid >> 6;   // g in 0..7
            const int ge = base + e;
            int r = 0, c = 0;
            if (ge < E) {
                if (is64) {
                    const long long* pe = (const long long*)edges;
                    r = (int)pe[ge]; c = (int)pe[(size_t)E + ge];
                } else {
                    const int* pe = (const int*)edges;
                    r = pe[ge]; c = pe[(size_t)E + ge];
                }
            }
            if (g == 0) { rows[e] = r; cols[e] = c; }
            if (g < 4) {
                // radial exps (4 per thread-group; si<15)
                float dx = coord[r * 3 + 0] - coord[c * 3 + 0];
                float dy = coord[r * 3 + 1] - coord[c * 3 + 1];
                float dz = coord[r * 3 + 2] - coord[c * 3 + 2];
                float nrm = sqrtf(dx * dx + dy * dy + dz * dz);
                float inv = __fdividef(1.0f, nrm + 1e-8f);
                float cx = dx * inv, cy = dy * inv, cz = dz * inv;
                if (g == 0 && ge < E) {
                    out[cdO + (size_t)ge * 3 + 0] = cx;
                    out[cdO + (size_t)ge * 3 + 1] = cy;
                    out[cdO + (size_t)ge * 3 + 2] = cz;
                }
                float ir = cx * cx + cy * cy + cz * cz;
#pragma unroll
                for (int s = 0; s < 4; s++) {
                    int si = g * 4 + s;
                    if (si < 15) {
                        float v = __expf(ir * c_scales[si]);
                        __half hh = __float2half_rn(v);
                        PH[e * 40 + 5 + si] = hh;
                        PL[e * 40 + 5 + si] = __float2half_rn(v - __half2float(hh));
                    }
                }
                if (g == 1) {
                    // zero pad k = 20..31
#pragma unroll
                    for (int k = 20; k < 32; k += 2) {
                        *(__half2*)(PH + e * 40 + k) =
                            __halves2half2(__float2half_rn(0.f), __float2half_rn(0.f));
                        *(__half2*)(PL + e * 40 + k) =
                            __halves2half2(__float2half_rn(0.f), __float2half_rn(0.f));
                    }
                }
            } else {
                // nprods: g=4 -> k2 0 and 4; g=5,6,7 -> k2 1,2,3
                int k2 = g - 4;
                for (int rep = 0; rep < 2; rep++) {
                    if (rep == 1) {
                        if (g != 4) break;
                        k2 = 4;
                    }
                    const float* av = &nvecs[((size_t)r * 5 + k2) * 3];
                    const float* bv = &nvecs[((size_t)c * 5 + k2) * 3];
                    float v = av[0] * bv[0] + av[1] * bv[1] + av[2] * bv[2];
                    __half hh = __float2half_rn(v);
                    PH[e * 40 + k2] = hh;
                    PL[e * 40 + k2] = __float2half_rn(v - __half2float(hh));
                }
            }
        }
        __syncthreads();   // S1

        // ---- Phase B: a1 = silu(P[r]+Q[c]+cb1) -> bufA hi/lo (8 thr/edge) ----
        {
            const int e = tid >> 3;
            const int k0 = (tid & 7) * 16;
            const int r = rows[e], c = cols[e];
            const float* Pr = g_P + (size_t)r * 128;
            const float* Qc = g_Q + (size_t)c * 128;
            __half2* AH = (__half2*)(smem + SM_AHI + e * 272 + k0 * 2);
            __half2* AL = (__half2*)(smem + SM_ALO + e * 272 + k0 * 2);
#pragma unroll
            for (int j = 0; j < 16; j += 2) {
                float2 pp = *(const float2*)(Pr + k0 + j);
                float2 qq = *(const float2*)(Qc + k0 + j);
                float v0 = siluf(pp.x + qq.x + cb1s[k0 + j]);
                float v1 = siluf(pp.y + qq.y + cb1s[k0 + j + 1]);
                __half h0 = __float2half_rn(v0), h1 = __float2half_rn(v1);
                AH[j >> 1] = __halves2half2(h0, h1);
                AL[j >> 1] = __halves2half2(__float2half_rn(v0 - __half2float(h0)),
                                            __float2half_rn(v1 - __half2float(h1)));
            }
        }
        __syncthreads();   // S2

        // ---- GEMM1: u1_pre = posin @ pw1 ; chem_pre = a1 @ cw2 ----
        float accU[4][4], accC[4][4];
#pragma unroll
        for (int b = 0; b < 4; b++)
#pragma unroll
            for (int q = 0; q < 4; q++) { accU[b][q] = 0.0f; accC[b][q] = 0.0f; }
        gemm64(sb0 + SM_PHI, sb0 + SM_PLO, sb0 + SM_PW1, 2, mw, nw, lane, accU, 80, 80);
        gemm64(sb0 + SM_AHI, sb0 + SM_ALO, sb0 + SM_WC, 8, mw, nw, lane, accC, 272, 272);
        __syncthreads();   // S3: all GEMM1 reads of bufA/bufP done

        // ---- Epilogue A: chem -> gmem + bufA; u1 -> bufU ----
#pragma unroll
        for (int ni = 0; ni < 4; ni++) {
            float* cc_ = accC[ni];
            float* cu_ = accU[ni];
            int rrow = mw * 16 + (lane >> 2);
            int cc = nw * 32 + ni * 8 + 2 * (lane & 3);
            float v00 = siluf(cc_[0] + cb2s[cc]);
            float v01 = siluf(cc_[1] + cb2s[cc + 1]);
            float v10 = siluf(cc_[2] + cb2s[cc]);
            float v11 = siluf(cc_[3] + cb2s[cc + 1]);
            int ge0 = base + rrow, ge1 = base + rrow + 8;
            if (ge0 < E) *(float2*)(out + chemO + (size_t)ge0 * 128 + cc) = make_float2(v00, v01);
            if (ge1 < E) *(float2*)(out + chemO + (size_t)ge1 * 128 + cc) = make_float2(v10, v11);
            __half h;
            h = __float2half_rn(v00);
            *(__half2*)(smem + SM_AHI + rrow * 272 + cc * 2) = __halves2half2(h, __float2half_rn(v01));
            *(__half2*)(smem + SM_ALO + rrow * 272 + cc * 2) =
                __halves2half2(__float2half_rn(v00 - __half2float(h)),
                               __float2half_rn(v01 - __half2float(__float2half_rn(v01))));
            h = __float2half_rn(v10);
            *(__half2*)(smem + SM_AHI + (rrow + 8) * 272 + cc * 2) = __halves2half2(h, __float2half_rn(v11));
            *(__half2*)(smem + SM_ALO + (rrow + 8) * 272 + cc * 2) =
                __halves2half2(__float2half_rn(v10 - __half2float(h)),
                               __float2half_rn(v11 - __half2float(__float2half_rn(v11))));
            float u00 = siluf(cu_[0] + pb1s[cc]);
            float u01 = siluf(cu_[1] + pb1s[cc + 1]);
            float u10 = siluf(cu_[2] + pb1s[cc]);
            float u11 = siluf(cu_[3] + pb1s[cc + 1]);
            h = __float2half_rn(u00);
            *(__half2*)(smem + SM_UHI + rrow * 272 + cc * 2) = __halves2half2(h, __float2half_rn(u01));
            *(__half2*)(smem + SM_ULO + rrow * 272 + cc * 2) =
                __halves2half2(__float2half_rn(u00 - __half2float(h)),
                               __float2half_rn(u01 - __half2float(__float2half_rn(u01))));
            h = __float2half_rn(u10);
            *(__half2*)(smem + SM_UHI + (rrow + 8) * 272 + cc * 2) = __halves2half2(h, __float2half_rn(u11));
            *(__half2*)(smem + SM_ULO + (rrow + 8) * 272 + cc * 2) =
                __halves2half2(__float2half_rn(u10 - __half2float(h)),
                               __float2half_rn(u11 - __half2float(__float2half_rn(u11))));
        }
        __syncthreads();   // S4

        // ---- GEMM2: pos_pre = u1 @ pw2 ; gate_pre = chem @ sw ----
        float accP4[4][4], accG[4][4];
#pragma unroll
        for (int b = 0; b < 4; b++)
#pragma unroll
            for (int q = 0; q < 4; q++) { accP4[b][q] = 0.0f; accG[b][q] = 0.0f; }
        gemm64(sb0 + SM_UHI, sb0 + SM_ULO, sb0 + SM_WP2, 8, mw, nw, lane, accP4, 272, 272);
        gemm64(sb0 + SM_AHI, sb0 + SM_ALO, sb0 + SM_WS, 8, mw, nw, lane, accG, 272, 272);

        // ---- Epilogue B part 1: pos -> gmem; gate*pos; att partials ----
        float rs0 = 0.0f, rs1 = 0.0f;
#pragma unroll
        for (int ni = 0; ni < 4; ni++) {
            float* cp_ = accP4[ni];
            float* cg = accG[ni];
            int rrow = mw * 16 + (lane >> 2);
            int cc = nw * 32 + ni * 8 + 2 * (lane & 3);
            float p00 = siluf(cp_[0] + pb2s[cc]);
            float p01 = siluf(cp_[1] + pb2s[cc + 1]);
            float p10 = siluf(cp_[2] + pb2s[cc]);
            float p11 = siluf(cp_[3] + pb2s[cc + 1]);
            int ge0 = base + rrow, ge1 = base + rrow + 8;
            if (ge0 < E) *(float2*)(out + posO + (size_t)ge0 * 128 + cc) = make_float2(p00, p01);
            if (ge1 < E) *(float2*)(out + posO + (size_t)ge1 * 128 + cc) = make_float2(p10, p11);
            float g00 = siluf(cg[0] + sbs[cc])     * p00;
            float g01 = siluf(cg[1] + sbs[cc + 1]) * p01;
            float g10 = siluf(cg[2] + sbs[cc])     * p10;
            float g11 = siluf(cg[3] + sbs[cc + 1]) * p11;
            cg[0] = g00; cg[1] = g01; cg[2] = g10; cg[3] = g11;
            rs0 += g00 * aws[cc] + g01 * aws[cc + 1];
            rs1 += g10 * aws[cc] + g11 * aws[cc + 1];
        }
        rs0 += __shfl_xor_sync(0xffffffffu, rs0, 1);
        rs0 += __shfl_xor_sync(0xffffffffu, rs0, 2);
        rs1 += __shfl_xor_sync(0xffffffffu, rs1, 1);
        rs1 += __shfl_xor_sync(0xffffffffu, rs1, 2);
        if ((lane & 3) == 0) {
            int row = mw * 16 + (lane >> 2);
            attPs[nw * 64 + row] = rs0;
            attPs[nw * 64 + row + 8] = rs1;
        }
        __syncthreads();   // S5

        // ---- Epilogue B part 2: att; final store ----
        int row0 = mw * 16 + (lane >> 2);
        float att0 = sigmoidf(attPs[row0] + attPs[64 + row0] +
                              attPs[128 + row0] + attPs[192 + row0] + abv);
        float att1 = sigmoidf(attPs[row0 + 8] + attPs[64 + row0 + 8] +
                              attPs[128 + row0 + 8] + attPs[192 + row0 + 8] + abv);
#pragma unroll
        for (int ni = 0; ni < 4; ni++) {
            float* cg = accG[ni];
            int cc = nw * 32 + ni * 8 + 2 * (lane & 3);
            int ge0 = base + row0, ge1 = base + row0 + 8;
            if (ge0 < E) *(float2*)(out + (size_t)ge0 * 128 + cc) =
                make_float2(cg[0] * att0, cg[1] * att0);
            if (ge1 < E) *(float2*)(out + (size_t)ge1 * 128 + cc) =
                make_float2(cg[2] * att1, cg[3] * att1);
        }
        __syncthreads();   // S6: protect buffer reuse next tile
    }
}

// ===================== launch =====================
extern "C" void kernel_launch(void* const* d_in, const int* in_sizes, int n_in,
                              void* d_out, int out_size) {
    const float* h     = (const float*)d_in[0];
    const float* coord = (const float*)d_in[1];
    const float* nvecs = (const float*)d_in[2];
    const float* na    = (const float*)d_in[3];
    const float* cw1   = (const float*)d_in[4];
    const float* cb1   = (const float*)d_in[5];
    const float* cw2   = (const float*)d_in[6];
    const float* cb2   = (const float*)d_in[7];
    const float* pw1   = (const float*)d_in[8];
    const float* pb1   = (const float*)d_in[9];
    const float* pw2   = (const float*)d_in[10];
    const float* pb2   = (const float*)d_in[11];
    const float* sw    = (const float*)d_in[12];
    const float* sb    = (const float*)d_in[13];
    const float* aw    = (const float*)d_in[14];
    const float* ab    = (const float*)d_in[15];
    const void*  edges = d_in[16];

    const int N = in_sizes[0] / NF;
    const int E = out_size / 387;   // out, chem, pos (128 each) + cd (3)
    float* out = (float*)d_out;

    cudaFuncSetAttribute(edge_hmma_kernel,
                         cudaFuncAttributeMaxDynamicSharedMemorySize, SMEM_BYTES);

    int nprobe = (E < 1024) ? E : 1024;
    detect_kernel<<<1, 256>>>((const int*)edges, nprobe);
    prep_weights<<<(3 * 16384 + 4096 + 255) / 256, 256>>>(cw2, pw2, sw, pw1);
    node_pre<<<(N + 15) / 16, 128>>>(h, na, cw1, N);

    const int nTiles = (E + TE - 1) / TE;
    const int grid = nTiles < 148 ? nTiles : 148;
    edge_hmma_kernel<<<grid, THREADS, SMEM_BYTES>>>(
        coord, nvecs, cb1, cb2, pb1, pb2, sb, aw, ab, edges, E, out);
}